// round 4
// baseline (speedup 1.0000x reference)
#include <cuda_runtime.h>

typedef unsigned long long u64;

#define NQ     14
#define DIM    16384
#define NL     6
#define NTHR   512

// ---------------- packed f32x2 helpers (PTX-only on sm_103a) ----------------
__device__ __forceinline__ u64 pk2(float x, float y) {
    u64 r; asm("mov.b64 %0,{%1,%2};" : "=l"(r) : "f"(x), "f"(y)); return r;
}
__device__ __forceinline__ void upk2(u64 v, float& x, float& y) {
    asm("mov.b64 {%0,%1},%2;" : "=f"(x), "=f"(y) : "l"(v));
}
__device__ __forceinline__ u64 mul2(u64 a, u64 b) {
    u64 r; asm("mul.rn.f32x2 %0,%1,%2;" : "=l"(r) : "l"(a), "l"(b)); return r;
}
__device__ __forceinline__ u64 fma2(u64 a, u64 b, u64 c) {
    u64 r; asm("fma.rn.f32x2 %0,%1,%2,%3;" : "=l"(r) : "l"(a), "l"(b), "l"(c)); return r;
}
__device__ __forceinline__ u64 swap2(u64 a) {
    u64 r;
    asm("{\n\t.reg .f32 x,y;\n\tmov.b64 {x,y},%1;\n\tmov.b64 %0,{y,x};\n\t}"
        : "=l"(r) : "l"(a));
    return r;
}

// CNOT-ring permutation (GF(2)-linear): bits 0..12 = suffix-XOR, bit13 = XOR(0..12)
__device__ __forceinline__ unsigned Pfold(unsigned i) {
    unsigned z = i ^ (i >> 1);
    z ^= z >> 2; z ^= z >> 4; z ^= z >> 8;
    return (z & 0x1FFFu) | (((z ^ (i >> 13)) & 1u) << 13);
}
// float-word swizzle: XOR bits 1-4 with bits 5-8 (keeps bit0 -> u64 pairs intact)
__device__ __forceinline__ unsigned ssf(unsigned f) {
    return f ^ ((((f) >> 5) & 15u) << 1);
}

// packed RX gate on register-index mask RM over 16 packed pairs
#define GATE2(RM, C2, S2, NS2)                                              \
    _Pragma("unroll")                                                       \
    for (int k = 0; k < 16; ++k) {                                          \
        if (!(k & (RM))) {                                                  \
            const int k1 = k | (RM);                                        \
            u64 t0 = mul2((S2),  Ri[k1]);                                   \
            u64 t1 = mul2((NS2), Rr[k1]);                                   \
            u64 t2 = mul2((S2),  Ri[k]);                                    \
            u64 t3 = mul2((NS2), Rr[k]);                                    \
            Rr[k]  = fma2((C2), Rr[k],  t0);                                \
            Ri[k]  = fma2((C2), Ri[k],  t1);                                \
            Rr[k1] = fma2((C2), Rr[k1], t2);                                \
            Ri[k1] = fma2((C2), Ri[k1], t3);                                \
        }                                                                   \
    }

__global__ void __launch_bounds__(NTHR, 1)
qlayer_kernel(const float* __restrict__ x,
              const float* __restrict__ params,
              float* __restrict__ out)
{
    extern __shared__ __align__(16) float sm[];
    float* sre = sm;            // DIM floats (real)
    float* sim = sm + DIM;      // DIM floats (imag)
    u64*   dre = (u64*)sre;     // packed pairs on i-bit0
    u64*   dim_ = (u64*)sim;

    __shared__ float gc[NL * NQ];
    __shared__ float gs[NL * NQ];
    __shared__ float red[NQ];

    const int b = blockIdx.x;
    const int t = threadIdx.x;              // 9 bits
    const int lane   = t & 31;
    const int warp   = t >> 5;              // 4 bits
    const int lane03 = lane & 15;
    const int lane4  = lane >> 4;

    if (t < NL * NQ) {
        float h = 0.5f * params[t];
        gc[t] = cosf(h);
        gs[t] = sinf(h);
    }
    if (t < NQ) red[t] = 0.0f;

    // ---------------- init product state directly into pass-A registers --------
    // pass-A layout: i = (t<<5) | (k<<1) | b0 ; bit bb of i <-> qubit (13-bb)
    // amp(i) = m(i) * (-i)^popcount(i)
    u64 Rr[16], Ri[16];
    {
        float cx[NQ], sx[NQ];
#pragma unroll
        for (int q = 0; q < NQ; ++q) {
            float h = 0.5f * x[b * NQ + q];
            cx[q] = cosf(h);
            sx[q] = sinf(h);
        }
        float hm = 1.0f;                    // t bit kk -> i bit 5+kk -> qubit 8-kk
#pragma unroll
        for (int kk = 0; kk < 9; ++kk)
            hm *= ((t >> kk) & 1) ? sx[8 - kk] : cx[8 - kk];
        const int hp = __popc((unsigned)t) & 3;
        const float wr = (hp == 0) ? 1.0f : ((hp == 2) ? -1.0f : 0.0f);
        const float wi = (hp == 3) ? 1.0f : ((hp == 1) ? -1.0f : 0.0f);
#pragma unroll
        for (int k = 0; k < 16; ++k) {
            float m5 = hm;                  // k bit m -> i bit 1+m -> qubit 12-m
#pragma unroll
            for (int mm = 0; mm < 4; ++mm)
                m5 *= ((k >> mm) & 1) ? sx[12 - mm] : cx[12 - mm];
            float m0 = m5 * cx[13];         // b0 = 0
            float m1 = m5 * sx[13];         // b0 = 1
            const int ck = __popc((unsigned)k) & 3;   // compile-time per k
            float wkr, wki;
            if      (ck == 0) { wkr =  wr; wki =  wi; }
            else if (ck == 1) { wkr =  wi; wki = -wr; }
            else if (ck == 2) { wkr = -wr; wki = -wi; }
            else              { wkr = -wi; wki =  wr; }
            // amp0 = m0*w ; amp1 = m1*w*(-i)
            Rr[k] = pk2(m0 * wkr,  m1 * wki);
            Ri[k] = pk2(m0 * wki, -m1 * wkr);
        }
    }
    __syncthreads();

    // pass-C thread i-part: i bits 1-4 = lane03, bit 9 = lane4, bits 5-8 = warp
    const unsigned Cbase = ((unsigned)lane4 << 9) | ((unsigned)warp << 5) |
                           ((unsigned)lane03 << 1);
    const unsigned pbC  = Pfold(Cbase);
    const unsigned spbC = ssf(pbC);

#pragma unroll 1
    for (int l = 0; l < NL; ++l) {
        const float* lc = gc + l * NQ;
        const float* ls = gs + l * NQ;

        // ===== pass A : i = (t<<5)|(k<<1)|b0 ; gates on i bits 0..4 =====
        if (l > 0) {
#pragma unroll
            for (int k = 0; k < 16; ++k) {
                int du = (t << 4) | (k ^ (t & 15));
                Rr[k] = dre[du];
                Ri[k] = dim_[du];
            }
        }
        {   // gate on i bit0 (qubit 13): pack bit -> half swaps
            float c = lc[13], s = ls[13];
            u64 c2 = pk2(c, c), s2 = pk2(s, s), ns2 = pk2(-s, -s);
#pragma unroll
            for (int k = 0; k < 16; ++k) {
                u64 isw = swap2(Ri[k]);
                u64 rsw = swap2(Rr[k]);
                Rr[k] = fma2(c2, Rr[k], mul2(s2, isw));
                Ri[k] = fma2(c2, Ri[k], mul2(ns2, rsw));
            }
        }
#pragma unroll
        for (int m = 0; m < 4; ++m) {        // i bit 1+m -> qubit 12-m
            float c = lc[12 - m], s = ls[12 - m];
            u64 c2 = pk2(c, c), s2 = pk2(s, s), ns2 = pk2(-s, -s);
            GATE2(1 << m, c2, s2, ns2)
        }
#pragma unroll
        for (int k = 0; k < 16; ++k) {
            int du = (t << 4) | (k ^ (t & 15));
            dre[du] = Rr[k];
            dim_[du] = Ri[k];
        }
        __syncthreads();

        // ===== pass B : i = (warp<<10)|(lane4<<9)|(k<<5)|(lane03<<1)|b0 ;
        //        gates on i bits 5..8 =====
        {
            const int baseB = (warp << 9) | (lane4 << 8);
#pragma unroll
            for (int k = 0; k < 16; ++k) {
                int du = baseB | (k << 4) | (lane03 ^ k);
                Rr[k] = dre[du];
                Ri[k] = dim_[du];
            }
#pragma unroll
            for (int m = 0; m < 4; ++m) {    // i bit 5+m -> qubit 8-m
                float c = lc[8 - m], s = ls[8 - m];
                u64 c2 = pk2(c, c), s2 = pk2(s, s), ns2 = pk2(-s, -s);
                GATE2(1 << m, c2, s2, ns2)
            }
#pragma unroll
            for (int k = 0; k < 16; ++k) {
                int du = baseB | (k << 4) | (lane03 ^ k);
                dre[du] = Rr[k];
                dim_[du] = Ri[k];
            }
        }
        __syncthreads();

        // ===== pass C : i = (k<<10)|(lane4<<9)|(warp<<5)|(lane03<<1)|b0 ;
        //        gates on i bits 10..13 + shuffle gate on i bit 9 =====
        {
            const int baseC = (lane4 << 8) | (warp << 4) | (lane03 ^ warp);
#pragma unroll
            for (int k = 0; k < 16; ++k) {
                int du = (k << 9) | baseC;
                Rr[k] = dre[du];
                Ri[k] = dim_[du];
            }
            {   // shuffle gate on i bit 9 (qubit 4): partner = lane ^ 16
                float c = lc[4], s = ls[4];
                u64 c2 = pk2(c, c), s2 = pk2(s, s), ns2 = pk2(-s, -s);
#pragma unroll
                for (int k = 0; k < 16; ++k) {
                    u64 Rp = __shfl_xor_sync(0xffffffffu, Rr[k], 16);
                    u64 Ip = __shfl_xor_sync(0xffffffffu, Ri[k], 16);
                    Rr[k] = fma2(c2, Rr[k], mul2(s2, Ip));
                    Ri[k] = fma2(c2, Ri[k], mul2(ns2, Rp));
                }
            }
#pragma unroll
            for (int m = 0; m < 4; ++m) {    // i bit 10+m -> qubit 3-m
                float c = lc[3 - m], s = ls[3 - m];
                u64 c2 = pk2(c, c), s2 = pk2(s, s), ns2 = pk2(-s, -s);
                GATE2(1 << m, c2, s2, ns2)
            }
        }

        if (l < NL - 1) {
            __syncthreads();                 // all loads done before scatter
            // CNOT-ring permutation fused into the store:
            //   float addr = spbC ^ ssf(Pfold(k<<10) [^ 0x2001 for b0=1])
#pragma unroll
            for (int k = 0; k < 16; ++k) {
                unsigned pc0 = Pfold((unsigned)k << 10);    // compile-time
                unsigned a0 = spbC ^ ssf(pc0);
                unsigned a1 = spbC ^ ssf(pc0 ^ 0x2001u);
                float r0, r1, i0, i1;
                upk2(Rr[k], r0, r1);
                upk2(Ri[k], i0, i1);
                sre[a0] = r0;  sim[a0] = i0;
                sre[a1] = r1;  sim[a1] = i1;
            }
            __syncthreads();
        }
    }

    // ---------------- reduction from pass-C registers (final CNOT via signs) ----
    // val_q = sum_i (-1)^{bit(13-q) of P(i)} |amp_i|^2 ; P(i) = pbC ^ const(k,b0)
    {
        const u64 PPc = pk2( 1.0f,  1.0f);
        const u64 MMc = pk2(-1.0f, -1.0f);
        const u64 PMc = pk2( 1.0f, -1.0f);
        const u64 MPc = pk2(-1.0f,  1.0f);
        u64 acc[NQ];
#pragma unroll
        for (int q = 0; q < NQ; ++q) acc[q] = pk2(0.0f, 0.0f);

#pragma unroll
        for (int k = 0; k < 16; ++k) {
            u64 pr2 = fma2(Rr[k], Rr[k], mul2(Ri[k], Ri[k]));  // (|a0|^2,|a1|^2)
            unsigned pc0 = Pfold((unsigned)k << 10);           // compile-time
            unsigned pc1 = pc0 ^ 0x2001u;
#pragma unroll
            for (int q = 0; q < NQ; ++q) {
                const int bpos = 13 - q;
                const int b0b = (int)((pc0 >> bpos) & 1u);
                const int b1b = (int)((pc1 >> bpos) & 1u);
                u64 pat = b0b ? (b1b ? MMc : MPc) : (b1b ? PMc : PPc);
                acc[q] = fma2(pat, pr2, acc[q]);
            }
        }
#pragma unroll
        for (int q = 0; q < NQ; ++q) {
            float a0, a1;
            upk2(acc[q], a0, a1);
            float v = a0 + a1;
            v = ((pbC >> (13 - q)) & 1u) ? -v : v;  // thread-level sign factor
#pragma unroll
            for (int off = 16; off; off >>= 1)
                v += __shfl_xor_sync(0xffffffffu, v, off);
            if (lane == 0) atomicAdd(&red[q], v);
        }
    }
    __syncthreads();
    if (t < NQ)
        out[b * NQ + t] = red[t];
}

extern "C" void kernel_launch(void* const* d_in, const int* in_sizes, int n_in,
                              void* d_out, int out_size)
{
    const float* x      = (const float*)d_in[0];
    const float* params = (const float*)d_in[1];
    if (n_in >= 2 && in_sizes[0] == NL * NQ) {   // defensive order check
        const float* tmp = x; x = params; params = tmp;
    }
    float* out = (float*)d_out;

    cudaFuncSetAttribute(qlayer_kernel,
                         cudaFuncAttributeMaxDynamicSharedMemorySize,
                         2 * DIM * (int)sizeof(float));
    qlayer_kernel<<<512, NTHR, 2 * DIM * sizeof(float)>>>(x, params, out);
}